// round 1
// baseline (speedup 1.0000x reference)
#include <cuda_runtime.h>
#include <math.h>

// Problem constants (fixed shapes)
#define TT   2048        // B*N tokens
#define DD   1024        // feature dim
#define HN   8           // heads
#define KDIM 128         // key dim
#define NK   256         // num keys per half
#define KSEL 16          // top-k
#define QO   2048        // 2*HN*KDIM

// ---------------- scratch (device globals; no allocation allowed) ----------
__device__ float g_sum[DD];
__device__ float g_sumsq[DD];
__device__ float g_scale[DD];
__device__ float g_shift[DD];
__device__ float g_q[(size_t)TT * QO];                 // 16 MB
__device__ float g_sim[(size_t)2 * TT * HN * NK];      // 32 MB
__device__ float g_gate[(size_t)TT * HN * KSEL];
__device__ int   g_idx[(size_t)TT * HN * KSEL];

// ---------------- BN stats ----------------
__global__ void zero_stats() {
    int i = blockIdx.x * blockDim.x + threadIdx.x;
    if (i < DD) { g_sum[i] = 0.f; g_sumsq[i] = 0.f; }
}

// grid (32, 16), block 256: each block sums 32 cols x 128 rows
__global__ void bn_sum(const float* __restrict__ x) {
    int lane = threadIdx.x & 31;
    int ty   = threadIdx.x >> 5;           // 0..7
    int d    = blockIdx.x * 32 + lane;
    int t0   = blockIdx.y * 128;
    float s = 0.f, ss = 0.f;
    for (int r = ty; r < 128; r += 8) {
        float v = x[(size_t)(t0 + r) * DD + d];
        s += v; ss += v * v;
    }
    __shared__ float sh[8][32], sh2[8][32];
    sh[ty][lane] = s; sh2[ty][lane] = ss;
    __syncthreads();
    if (ty == 0) {
        float a = 0.f, b = 0.f;
        #pragma unroll
        for (int r = 0; r < 8; r++) { a += sh[r][lane]; b += sh2[r][lane]; }
        atomicAdd(&g_sum[d], a);
        atomicAdd(&g_sumsq[d], b);
    }
}

__global__ void bn_fin(const float* __restrict__ gamma, const float* __restrict__ beta) {
    int d = blockIdx.x * blockDim.x + threadIdx.x;
    if (d < DD) {
        float mean = g_sum[d] * (1.f / TT);
        float var  = g_sumsq[d] * (1.f / TT) - mean * mean;
        float rs   = rsqrtf(var + 1e-5f);
        float sc   = gamma[d] * rs;
        g_scale[d] = sc;
        g_shift[d] = beta[d] - mean * sc;
    }
}

// ---------------- q GEMM: q[t,o] = sum_d (x*scale+shift)[t,d] * Wq[d,o] ----
// C = A(2048x1024) * B(1024x2048). 128x128 tile, BK=8, 8x8 microtile.
__global__ void __launch_bounds__(256) qgemm(const float* __restrict__ x,
                                             const float* __restrict__ Wq) {
    __shared__ float As[8][128];
    __shared__ float Bs[8][128];
    int tid = threadIdx.x;
    int tx = tid & 15, ty = tid >> 4;
    int m0 = blockIdx.y * 128, n0 = blockIdx.x * 128;

    float acc[8][8];
    #pragma unroll
    for (int i = 0; i < 8; i++)
        #pragma unroll
        for (int j = 0; j < 8; j++) acc[i][j] = 0.f;

    int ar = tid >> 1, ac = (tid & 1) * 4;     // A: 128 rows x 8 cols
    int br = tid >> 5, bc = (tid & 31) * 4;    // B: 8 rows x 128 cols

    for (int k0 = 0; k0 < DD; k0 += 8) {
        float4 av = *(const float4*)(x + (size_t)(m0 + ar) * DD + k0 + ac);
        av.x = av.x * g_scale[k0 + ac + 0] + g_shift[k0 + ac + 0];
        av.y = av.y * g_scale[k0 + ac + 1] + g_shift[k0 + ac + 1];
        av.z = av.z * g_scale[k0 + ac + 2] + g_shift[k0 + ac + 2];
        av.w = av.w * g_scale[k0 + ac + 3] + g_shift[k0 + ac + 3];
        As[ac + 0][ar] = av.x; As[ac + 1][ar] = av.y;
        As[ac + 2][ar] = av.z; As[ac + 3][ar] = av.w;

        float4 bv = *(const float4*)(Wq + (size_t)(k0 + br) * QO + n0 + bc);
        *(float4*)&Bs[br][bc] = bv;
        __syncthreads();

        #pragma unroll
        for (int kk = 0; kk < 8; kk++) {
            float a[8], b[8];
            *(float4*)&a[0] = *(float4*)&As[kk][ty * 8];
            *(float4*)&a[4] = *(float4*)&As[kk][ty * 8 + 4];
            *(float4*)&b[0] = *(float4*)&Bs[kk][tx * 8];
            *(float4*)&b[4] = *(float4*)&Bs[kk][tx * 8 + 4];
            #pragma unroll
            for (int i = 0; i < 8; i++)
                #pragma unroll
                for (int j = 0; j < 8; j++)
                    acc[i][j] += a[i] * b[j];
        }
        __syncthreads();
    }

    #pragma unroll
    for (int i = 0; i < 8; i++) {
        float4 v0 = make_float4(acc[i][0], acc[i][1], acc[i][2], acc[i][3]);
        float4 v1 = make_float4(acc[i][4], acc[i][5], acc[i][6], acc[i][7]);
        float* cp = g_q + (size_t)(m0 + ty * 8 + i) * QO + n0 + tx * 8;
        *(float4*)(cp)     = v0;
        *(float4*)(cp + 4) = v1;
    }
}

// ---------------- sim GEMM: sim[p,t,h,k] = q[t, p*1024+h*128+:] . keys[h,k,p,:]
// grid (32 t-tiles, 4 key-tiles, 16 ph), block 256, 64x64 tile, BK=16, 4x4 micro
__global__ void __launch_bounds__(256) simgemm(const float* __restrict__ keys) {
    __shared__ float As[16][64];
    __shared__ float Bs[16][64];
    int tid = threadIdx.x;
    int ph = blockIdx.z; int p = ph >> 3, h = ph & 7;
    int t0 = blockIdx.x * 64, n0 = blockIdx.y * 64;
    int tx = tid & 15, ty = tid >> 4;

    float acc[4][4];
    #pragma unroll
    for (int i = 0; i < 4; i++)
        #pragma unroll
        for (int j = 0; j < 4; j++) acc[i][j] = 0.f;

    int ar = tid >> 2, ac = (tid & 3) * 4;     // 64 rows x 16 cols, 4/thread
    const float* qb = g_q + (size_t)t0 * QO + p * 1024 + h * 128;
    const float* kb = keys + ((size_t)(h * NK + n0) * 2 + p) * 128;

    for (int k0 = 0; k0 < 128; k0 += 16) {
        float4 av = *(const float4*)(qb + (size_t)ar * QO + k0 + ac);
        As[ac + 0][ar] = av.x; As[ac + 1][ar] = av.y;
        As[ac + 2][ar] = av.z; As[ac + 3][ar] = av.w;
        float4 bv = *(const float4*)(kb + (size_t)ar * 256 + k0 + ac);
        Bs[ac + 0][ar] = bv.x; Bs[ac + 1][ar] = bv.y;
        Bs[ac + 2][ar] = bv.z; Bs[ac + 3][ar] = bv.w;
        __syncthreads();

        #pragma unroll
        for (int kk = 0; kk < 16; kk++) {
            float a[4], b[4];
            *(float4*)&a[0] = *(float4*)&As[kk][ty * 4];
            *(float4*)&b[0] = *(float4*)&Bs[kk][tx * 4];
            #pragma unroll
            for (int i = 0; i < 4; i++)
                #pragma unroll
                for (int j = 0; j < 4; j++)
                    acc[i][j] += a[i] * b[j];
        }
        __syncthreads();
    }

    #pragma unroll
    for (int i = 0; i < 4; i++) {
        float4 v = make_float4(acc[i][0], acc[i][1], acc[i][2], acc[i][3]);
        *(float4*)(g_sim + ((size_t)(p * TT + t0 + ty * 4 + i) * HN + h) * NK + n0 + tx * 4) = v;
    }
}

// ---------------- top-k ----------------
__device__ __forceinline__ void warp_argmax(float& bv, int& bi) {
    #pragma unroll
    for (int off = 16; off; off >>= 1) {
        float ov = __shfl_xor_sync(0xffffffffu, bv, off);
        int   oi = __shfl_xor_sync(0xffffffffu, bi, off);
        if (ov > bv || (ov == bv && oi < bi)) { bv = ov; bi = oi; }
    }
}

// one warp per (t, h); grid 2048 blocks x 256 threads
__global__ void __launch_bounds__(256) topk_kernel() {
    int warp = threadIdx.x >> 5, lane = threadIdx.x & 31;
    int th = blockIdx.x * 8 + warp;      // 0..16383
    int t = th >> 3, h = th & 7;

    __shared__ float svx[8][16], svy[8][16];
    __shared__ int   six[8][16], siy[8][16];

    const float* sx = g_sim + ((size_t)t * HN + h) * NK;            // p = 0
    const float* sy = g_sim + ((size_t)(TT + t) * HN + h) * NK;     // p = 1

    float v[8];
    #pragma unroll
    for (int j = 0; j < 8; j++) v[j] = sx[j * 32 + lane];
    for (int it = 0; it < KSEL; it++) {
        float bv = -1e30f; int bi = 0x7fffffff;
        #pragma unroll
        for (int j = 0; j < 8; j++) {
            int id = j * 32 + lane;
            if (v[j] > bv) { bv = v[j]; bi = id; }
        }
        warp_argmax(bv, bi);
        if ((bi & 31) == lane) v[bi >> 5] = -1e30f;
        if (lane == 0) { svx[warp][it] = bv; six[warp][it] = bi; }
    }
    #pragma unroll
    for (int j = 0; j < 8; j++) v[j] = sy[j * 32 + lane];
    for (int it = 0; it < KSEL; it++) {
        float bv = -1e30f; int bi = 0x7fffffff;
        #pragma unroll
        for (int j = 0; j < 8; j++) {
            int id = j * 32 + lane;
            if (v[j] > bv) { bv = v[j]; bi = id; }
        }
        warp_argmax(bv, bi);
        if ((bi & 31) == lane) v[bi >> 5] = -1e30f;
        if (lane == 0) { svy[warp][it] = bv; siy[warp][it] = bi; }
    }
    __syncwarp();

    // cartesian 16x16, top-16 (candidate c = i*16 + j matches jax flatten order)
    float cv[8];
    #pragma unroll
    for (int j = 0; j < 8; j++) {
        int c = j * 32 + lane;
        cv[j] = svx[warp][c >> 4] + svy[warp][c & 15];
    }
    for (int it = 0; it < KSEL; it++) {
        float bv = -1e30f; int bi = 0x7fffffff;
        #pragma unroll
        for (int j = 0; j < 8; j++) {
            int c = j * 32 + lane;
            if (cv[j] > bv) { bv = cv[j]; bi = c; }
        }
        warp_argmax(bv, bi);
        if ((bi & 31) == lane) cv[bi >> 5] = -1e30f;
        if (lane == 0) {
            int i = bi >> 4, jj = bi & 15;
            g_gate[(size_t)th * KSEL + it] = 1.f / (1.f + expf(-bv));
            g_idx[(size_t)th * KSEL + it]  = six[warp][i] * NK + siy[warp][jj];
        }
    }
}

// ---------------- expert gather + down/up ----------------
// one block per token; warp w handles head w's 16 experts
__global__ void __launch_bounds__(256) gather_kernel(const float* __restrict__ x,
                                                     const float* __restrict__ down_w,
                                                     const float* __restrict__ up_w,
                                                     float* __restrict__ out) {
    int t = blockIdx.x;
    int tid = threadIdx.x, lane = tid & 31, w = tid >> 5;

    __shared__ float xs[DD];
    __shared__ float outs[DD];
    for (int i = tid; i < DD; i += 256) { xs[i] = x[(size_t)t * DD + i]; outs[i] = 0.f; }
    __syncthreads();

    float4 a4[8];
    #pragma unroll
    for (int j = 0; j < 8; j++) a4[j] = make_float4(0.f, 0.f, 0.f, 0.f);

    int base = t * (HN * KSEL) + w * KSEL;
    for (int k = 0; k < KSEL; k++) {
        int   idx  = g_idx[base + k];
        float gate = g_gate[base + k];
        const float4* dr = (const float4*)(down_w + (size_t)idx * DD) + lane;
        const float4* ur = (const float4*)(up_w   + (size_t)idx * DD) + lane;

        float s0 = 0.f, s1 = 0.f, s2 = 0.f, s3 = 0.f;
        #pragma unroll
        for (int j = 0; j < 8; j++) {
            float4 xv = *(const float4*)&xs[j * 128 + lane * 4];
            float4 dv = dr[j * 32];
            s0 += xv.x * dv.x; s1 += xv.y * dv.y;
            s2 += xv.z * dv.z; s3 += xv.w * dv.w;
        }
        float s = (s0 + s1) + (s2 + s3);
        #pragma unroll
        for (int off = 16; off; off >>= 1) s += __shfl_xor_sync(0xffffffffu, s, off);

        float hv = gate * 0.5f * s * (1.f + erff(s * 0.70710678118f));   // sigmoid(score)*gelu_exact

        #pragma unroll
        for (int j = 0; j < 8; j++) {
            float4 uv = ur[j * 32];
            a4[j].x += hv * uv.x; a4[j].y += hv * uv.y;
            a4[j].z += hv * uv.z; a4[j].w += hv * uv.w;
        }
    }

    // combine 8 warps' partials
    for (int ww = 0; ww < 8; ww++) {
        if (w == ww) {
            #pragma unroll
            for (int j = 0; j < 8; j++) {
                float4* o = (float4*)&outs[j * 128 + lane * 4];
                float4 v = *o;
                v.x += a4[j].x; v.y += a4[j].y; v.z += a4[j].z; v.w += a4[j].w;
                *o = v;
            }
        }
        __syncthreads();
    }
    for (int i = tid; i < DD; i += 256) out[(size_t)t * DD + i] = outs[i];
}

// ---------------- launch ----------------
extern "C" void kernel_launch(void* const* d_in, const int* in_sizes, int n_in,
                              void* d_out, int out_size) {
    const float* x      = (const float*)d_in[0];   // [2,1024,1024]
    const float* gamma  = (const float*)d_in[1];   // [1024]
    const float* beta   = (const float*)d_in[2];   // [1024]
    const float* Wq     = (const float*)d_in[3];   // [1024,2048]
    const float* keys   = (const float*)d_in[4];   // [8,256,2,128]
    const float* down_w = (const float*)d_in[5];   // [65536,1024]
    const float* up_w   = (const float*)d_in[6];   // [65536,1024]
    float* out = (float*)d_out;                    // [2,1024,1024]

    zero_stats<<<4, 256>>>();
    bn_sum<<<dim3(32, 16), 256>>>(x);
    bn_fin<<<4, 256>>>(gamma, beta);
    qgemm<<<dim3(16, 16), 256>>>(x, Wq);
    simgemm<<<dim3(32, 4, 16), 256>>>(keys);
    topk_kernel<<<2048, 256>>>();
    gather_kernel<<<2048, 256>>>(x, down_w, up_w, out);
}